// round 2
// baseline (speedup 1.0000x reference)
#include <cuda_runtime.h>
#include <cstddef>

#define B_ 4
#define T_ 1024
#define D_ 512
#define H_ 16
#define DH_ 32
#define BT_ (B_ * T_)

typedef unsigned long long u64;

// ---- f32x2 packed-math helpers (sm_103a) ----
__device__ __forceinline__ u64 pack2(float x, float y) {
  u64 r; asm("mov.b64 %0, {%1, %2};" : "=l"(r) : "f"(x), "f"(y)); return r;
}
__device__ __forceinline__ void fma2(u64& d, u64 a, u64 b) {
  asm("fma.rn.f32x2 %0, %1, %2, %0;" : "+l"(d) : "l"(a), "l"(b));
}
__device__ __forceinline__ float2 unpack2(u64 v) {
  float2 f; asm("mov.b64 {%0, %1}, %2;" : "=f"(f.x), "=f"(f.y) : "l"(v)); return f;
}

// ---- scratch (static device globals; no runtime allocation) ----
__device__ float g_qh[BT_ * D_];
__device__ float g_kh[BT_ * D_];
__device__ float g_vh[BT_ * D_];
__device__ float g_ph[BT_ * D_];
__device__ float g_ctx[BT_ * D_];
__device__ float g_P[(size_t)B_ * H_ * T_ * T_];  // 256 MB, unshifted pos scores

// =====================================================================
// GEMM: C[M x 512] = A[M x 512] @ W[512 x 512] (+ bias), M = 4096.
// Tile 128x64, BK=16, 256 threads, 8x4 per thread, f32x2 packed FMAs.
// sel: 0..3 -> C is g_qh/g_kh/g_vh/g_ph ; 4 -> A is g_ctx, C is Cext.
// =====================================================================
__global__ __launch_bounds__(256) void gemm512_kernel(
    const float* __restrict__ Aext, const float* __restrict__ W,
    const float* __restrict__ bias, float* __restrict__ Cext, int sel) {
  const float* A = (sel == 4) ? g_ctx : Aext;
  float* C = (sel == 0) ? g_qh : (sel == 1) ? g_kh : (sel == 2) ? g_vh
           : (sel == 3) ? g_ph : Cext;

  __shared__ float As[16][132];  // [k][m], 528B rows (16B aligned)
  __shared__ float Bs[16][68];   // [k][n]

  const int tid = threadIdx.x;
  const int tx = tid & 15, ty = tid >> 4;          // tx: n-group (4), ty: m-group (8)
  const int m0 = blockIdx.y * 128, n0 = blockIdx.x * 64;

  u64 acc[4][4];  // [m-pair][n]
#pragma unroll
  for (int i = 0; i < 4; i++)
#pragma unroll
    for (int j = 0; j < 4; j++) acc[i][j] = 0ull;

  for (int k0 = 0; k0 < 512; k0 += 16) {
    // A tile: 128 m x 16 k = 512 float4 along k; 2 per thread, store transposed
#pragma unroll
    for (int r = 0; r < 2; r++) {
      int idx = tid + r * 256;
      int m = idx >> 2, kq = (idx & 3) * 4;
      float4 a4 = *reinterpret_cast<const float4*>(&A[(size_t)(m0 + m) * 512 + k0 + kq]);
      As[kq + 0][m] = a4.x; As[kq + 1][m] = a4.y;
      As[kq + 2][m] = a4.z; As[kq + 3][m] = a4.w;
    }
    // B tile: 16 k x 64 n = 256 float4; 1 per thread, direct
    {
      int kr = tid >> 4, nc = (tid & 15) * 4;
      *reinterpret_cast<float4*>(&Bs[kr][nc]) =
          *reinterpret_cast<const float4*>(&W[(size_t)(k0 + kr) * 512 + n0 + nc]);
    }
    __syncthreads();
#pragma unroll
    for (int kk = 0; kk < 16; kk++) {
      ulonglong2 a01 = *reinterpret_cast<const ulonglong2*>(&As[kk][ty * 8]);
      ulonglong2 a23 = *reinterpret_cast<const ulonglong2*>(&As[kk][ty * 8 + 4]);
      float4 b4 = *reinterpret_cast<const float4*>(&Bs[kk][tx * 4]);
      u64 b0 = pack2(b4.x, b4.x), b1 = pack2(b4.y, b4.y);
      u64 b2 = pack2(b4.z, b4.z), b3 = pack2(b4.w, b4.w);
      fma2(acc[0][0], a01.x, b0); fma2(acc[0][1], a01.x, b1);
      fma2(acc[0][2], a01.x, b2); fma2(acc[0][3], a01.x, b3);
      fma2(acc[1][0], a01.y, b0); fma2(acc[1][1], a01.y, b1);
      fma2(acc[1][2], a01.y, b2); fma2(acc[1][3], a01.y, b3);
      fma2(acc[2][0], a23.x, b0); fma2(acc[2][1], a23.x, b1);
      fma2(acc[2][2], a23.x, b2); fma2(acc[2][3], a23.x, b3);
      fma2(acc[3][0], a23.y, b0); fma2(acc[3][1], a23.y, b1);
      fma2(acc[3][2], a23.y, b2); fma2(acc[3][3], a23.y, b3);
    }
    __syncthreads();
  }

  float4 bb = make_float4(0.f, 0.f, 0.f, 0.f);
  if (bias) bb = *reinterpret_cast<const float4*>(&bias[n0 + tx * 4]);
#pragma unroll
  for (int i = 0; i < 4; i++) {
    float2 p0 = unpack2(acc[i][0]), p1 = unpack2(acc[i][1]);
    float2 p2 = unpack2(acc[i][2]), p3 = unpack2(acc[i][3]);
    float4 r0 = make_float4(p0.x + bb.x, p1.x + bb.y, p2.x + bb.z, p3.x + bb.w);
    float4 r1 = make_float4(p0.y + bb.x, p1.y + bb.y, p2.y + bb.z, p3.y + bb.w);
    const int m = m0 + ty * 8 + 2 * i;
    *reinterpret_cast<float4*>(&C[(size_t)m * 512 + n0 + tx * 4]) = r0;
    *reinterpret_cast<float4*>(&C[(size_t)(m + 1) * 512 + n0 + tx * 4]) = r1;
  }
}

// =====================================================================
// Pos score GEMM: P[bh, t, j] = sum_d (qh[b,t,h,d] + v_bias[h,d]) * ph[b,j,h,d]
// =====================================================================
__global__ __launch_bounds__(256) void pscore_kernel(const float* __restrict__ vbias) {
  __shared__ float As[32][68];
  __shared__ float Bs[32][68];
  const int tid = threadIdx.x;
  const int bz = blockIdx.z, b = bz >> 4, h = bz & 15;
  const int t0 = blockIdx.y * 64, j0 = blockIdx.x * 64;

  const int e0 = tid * 2;
#pragma unroll
  for (int e = e0; e < e0 + 2; e++) {
    const int r = e >> 3, seg = (e & 7) * 4;
    float4 a4 = *reinterpret_cast<const float4*>(
        &g_qh[(size_t)(b * T_ + t0 + r) * D_ + h * DH_ + seg]);
    float4 vbv = *reinterpret_cast<const float4*>(&vbias[h * DH_ + seg]);
    float4 b4 = *reinterpret_cast<const float4*>(
        &g_ph[(size_t)(b * T_ + j0 + r) * D_ + h * DH_ + seg]);
    As[seg + 0][r] = a4.x + vbv.x; As[seg + 1][r] = a4.y + vbv.y;
    As[seg + 2][r] = a4.z + vbv.z; As[seg + 3][r] = a4.w + vbv.w;
    Bs[seg + 0][r] = b4.x; Bs[seg + 1][r] = b4.y;
    Bs[seg + 2][r] = b4.z; Bs[seg + 3][r] = b4.w;
  }
  __syncthreads();

  const int tx = tid & 15, ty = tid >> 4;
  u64 acc[4][2];
#pragma unroll
  for (int i = 0; i < 4; i++) { acc[i][0] = 0ull; acc[i][1] = 0ull; }
#pragma unroll
  for (int kk = 0; kk < 32; kk++) {
    float4 a = *reinterpret_cast<const float4*>(&As[kk][ty * 4]);
    ulonglong2 b2 = *reinterpret_cast<const ulonglong2*>(&Bs[kk][tx * 4]);
    u64 a0 = pack2(a.x, a.x), a1 = pack2(a.y, a.y);
    u64 a2 = pack2(a.z, a.z), a3 = pack2(a.w, a.w);
    fma2(acc[0][0], a0, b2.x); fma2(acc[0][1], a0, b2.y);
    fma2(acc[1][0], a1, b2.x); fma2(acc[1][1], a1, b2.y);
    fma2(acc[2][0], a2, b2.x); fma2(acc[2][1], a2, b2.y);
    fma2(acc[3][0], a3, b2.x); fma2(acc[3][1], a3, b2.y);
  }

#pragma unroll
  for (int i = 0; i < 4; i++) {
    const int t = t0 + ty * 4 + i;
    float2 lo = unpack2(acc[i][0]), hi = unpack2(acc[i][1]);
    float4 o = make_float4(lo.x, lo.y, hi.x, hi.y);
    *reinterpret_cast<float4*>(&g_P[((size_t)bz * T_ + t) * T_ + j0 + tx * 4]) = o;
  }
}

// =====================================================================
// Fused content-score + relative-shift + softmax + AV.
// One block = one (b,h) x 32 query rows; full 1024-key sweep in smem.
//   smem: Ss[32][1028] scores | Qs[32][36] (k-major q+u) | KV (union K^T / V)
// shift(P)[t,s] = P[t, s-t+1023] (s<=t) ; 0 (s==t+1) ; P[t+1, s-t-2] (s>=t+2)
// =====================================================================
#define SS_STRIDE 1028
#define KS_STRIDE 132
#define VS_STRIDE 36
#define SMEM_ATTN_FLOATS (32 * SS_STRIDE + 32 * 36 + 128 * VS_STRIDE)

__global__ __launch_bounds__(256) void attn_fused_kernel(const float* __restrict__ ubias) {
  extern __shared__ float sm[];
  float* Ss = sm;                       // 32 x 1028
  float* Qs = sm + 32 * SS_STRIDE;      // 32 k x 36 t
  float* KV = Qs + 32 * 36;             // union: K^T 32x132 | V 128x36

  const int tid = threadIdx.x;
  const int bz = blockIdx.y, b = bz >> 4, h = bz & 15;
  const int t0 = blockIdx.x * 32;

  // ---- load Qs[k][t] = qh[b, t0+t, h, k] + u_bias[h, k] (transposed) ----
  {
    int t = tid & 31, kq = (tid >> 5) * 4;
    float4 q4 = *reinterpret_cast<const float4*>(
        &g_qh[(size_t)(b * T_ + t0 + t) * D_ + h * DH_ + kq]);
    float4 u4 = *reinterpret_cast<const float4*>(&ubias[h * DH_ + kq]);
    Qs[(kq + 0) * 36 + t] = q4.x + u4.x;
    Qs[(kq + 1) * 36 + t] = q4.y + u4.y;
    Qs[(kq + 2) * 36 + t] = q4.z + u4.z;
    Qs[(kq + 3) * 36 + t] = q4.w + u4.w;
  }

  // ---- score phase: 8 chunks of 128 keys ----
  const int sx = tid & 31, tyy = tid >> 5;  // thread tile: 4t x 4s
  const float isd = 0.04419417382415922f;   // 1/sqrt(512)

  for (int c = 0; c < 8; c++) {
    const int s0 = c * 128;
    // load K chunk transposed: KV[k][s]
#pragma unroll
    for (int r = 0; r < 4; r++) {
      int idx = tid + r * 256;
      int s = idx >> 3, kq = (idx & 7) * 4;
      float4 k4 = *reinterpret_cast<const float4*>(
          &g_kh[(size_t)(b * T_ + s0 + s) * D_ + h * DH_ + kq]);
      KV[(kq + 0) * KS_STRIDE + s] = k4.x;
      KV[(kq + 1) * KS_STRIDE + s] = k4.y;
      KV[(kq + 2) * KS_STRIDE + s] = k4.z;
      KV[(kq + 3) * KS_STRIDE + s] = k4.w;
    }
    __syncthreads();

    u64 acc[4][2];
#pragma unroll
    for (int i = 0; i < 4; i++) { acc[i][0] = 0ull; acc[i][1] = 0ull; }
#pragma unroll
    for (int kk = 0; kk < 32; kk++) {
      float4 a4 = *reinterpret_cast<const float4*>(&Qs[kk * 36 + tyy * 4]);
      ulonglong2 b2 = *reinterpret_cast<const ulonglong2*>(&KV[kk * KS_STRIDE + sx * 4]);
      u64 a0 = pack2(a4.x, a4.x), a1 = pack2(a4.y, a4.y);
      u64 a2 = pack2(a4.z, a4.z), a3 = pack2(a4.w, a4.w);
      fma2(acc[0][0], a0, b2.x); fma2(acc[0][1], a0, b2.y);
      fma2(acc[1][0], a1, b2.x); fma2(acc[1][1], a1, b2.y);
      fma2(acc[2][0], a2, b2.x); fma2(acc[2][1], a2, b2.y);
      fma2(acc[3][0], a3, b2.x); fma2(acc[3][1], a3, b2.y);
    }

#pragma unroll
    for (int i = 0; i < 4; i++) {
      const int trow = tyy * 4 + i;
      const int t = t0 + trow;
      const size_t rowb = ((size_t)bz * T_ + t) * T_;
      float2 lo = unpack2(acc[i][0]), hi = unpack2(acc[i][1]);
      float v[4] = {lo.x, lo.y, hi.x, hi.y};
#pragma unroll
      for (int j = 0; j < 4; j++) {
        const int s = s0 + sx * 4 + j;
        float pv;
        if (s <= t)          pv = g_P[rowb + (s - t + (T_ - 1))];
        else if (s == t + 1) pv = 0.f;
        else                 pv = g_P[rowb + T_ + (s - t - 2)];
        v[j] = (v[j] + pv) * isd;
      }
      *reinterpret_cast<float4*>(&Ss[trow * SS_STRIDE + s0 + sx * 4]) =
          make_float4(v[0], v[1], v[2], v[3]);
    }
    __syncthreads();
  }

  // ---- softmax: warp w owns rows 4w..4w+3 (exactly the rows it wrote) ----
  {
    const int w = tid >> 5, lane = tid & 31;
#pragma unroll
    for (int rr = 0; rr < 4; rr++) {
      float* row = Ss + (w * 4 + rr) * SS_STRIDE;
      float4 x[8];
      float m = -3.4e38f;
#pragma unroll
      for (int i = 0; i < 8; i++) {
        x[i] = *reinterpret_cast<float4*>(&row[lane * 4 + i * 128]);
        m = fmaxf(m, fmaxf(fmaxf(x[i].x, x[i].y), fmaxf(x[i].z, x[i].w)));
      }
#pragma unroll
      for (int o = 16; o > 0; o >>= 1) m = fmaxf(m, __shfl_xor_sync(0xffffffffu, m, o));
      float s = 0.f;
#pragma unroll
      for (int i = 0; i < 8; i++) {
        x[i].x = __expf(x[i].x - m); x[i].y = __expf(x[i].y - m);
        x[i].z = __expf(x[i].z - m); x[i].w = __expf(x[i].w - m);
        s += (x[i].x + x[i].y) + (x[i].z + x[i].w);
      }
#pragma unroll
      for (int o = 16; o > 0; o >>= 1) s += __shfl_xor_sync(0xffffffffu, s, o);
      const float r = 1.0f / s;
#pragma unroll
      for (int i = 0; i < 8; i++) {
        x[i].x *= r; x[i].y *= r; x[i].z *= r; x[i].w *= r;
        *reinterpret_cast<float4*>(&row[lane * 4 + i * 128]) = x[i];
      }
    }
  }
  __syncthreads();

  // ---- AV phase: ctx[32 t][32 dh]; thread = 2t x 2dh ----
  const int tp = tid >> 4;        // 0..15 -> rows tp*2, tp*2+1
  const int dh = (tid & 15) * 2;  // dh pair
  const int tA = tp * 2;
  u64 o0 = 0ull, o1 = 0ull;

  for (int c = 0; c < 8; c++) {
    const int s0 = c * 128;
    // load V chunk: KV[s][dh] (not transposed)
#pragma unroll
    for (int r = 0; r < 4; r++) {
      int idx = tid + r * 256;
      int s = idx >> 3, kq = (idx & 7) * 4;
      *reinterpret_cast<float4*>(&KV[s * VS_STRIDE + kq]) =
          *reinterpret_cast<const float4*>(
              &g_vh[(size_t)(b * T_ + s0 + s) * D_ + h * DH_ + kq]);
    }
    __syncthreads();

    const float* rowA = &Ss[tA * SS_STRIDE + s0];
    const float* rowB = &Ss[(tA + 1) * SS_STRIDE + s0];
#pragma unroll 8
    for (int ss = 0; ss < 128; ss += 4) {
      float4 sa = *reinterpret_cast<const float4*>(&rowA[ss]);
      float4 sb = *reinterpret_cast<const float4*>(&rowB[ss]);
      u64 v0 = *reinterpret_cast<const u64*>(&KV[(ss + 0) * VS_STRIDE + dh]);
      u64 v1 = *reinterpret_cast<const u64*>(&KV[(ss + 1) * VS_STRIDE + dh]);
      u64 v2 = *reinterpret_cast<const u64*>(&KV[(ss + 2) * VS_STRIDE + dh]);
      u64 v3 = *reinterpret_cast<const u64*>(&KV[(ss + 3) * VS_STRIDE + dh]);
      fma2(o0, pack2(sa.x, sa.x), v0); fma2(o1, pack2(sb.x, sb.x), v0);
      fma2(o0, pack2(sa.y, sa.y), v1); fma2(o1, pack2(sb.y, sb.y), v1);
      fma2(o0, pack2(sa.z, sa.z), v2); fma2(o1, pack2(sb.z, sb.z), v2);
      fma2(o0, pack2(sa.w, sa.w), v3); fma2(o1, pack2(sb.w, sb.w), v3);
    }
    __syncthreads();
  }

  float2 f0 = unpack2(o0), f1 = unpack2(o1);
  *reinterpret_cast<float2*>(
      &g_ctx[(size_t)(b * T_ + t0 + tA) * D_ + h * DH_ + dh]) = f0;
  *reinterpret_cast<float2*>(
      &g_ctx[(size_t)(b * T_ + t0 + tA + 1) * D_ + h * DH_ + dh]) = f1;
}

// =====================================================================
extern "C" void kernel_launch(void* const* d_in, const int* in_sizes, int n_in,
                              void* d_out, int out_size) {
  const float* q   = (const float*)d_in[0];
  const float* k   = (const float*)d_in[1];
  const float* v   = (const float*)d_in[2];
  const float* pos = (const float*)d_in[3];
  const float* Wq  = (const float*)d_in[4];
  const float* bq  = (const float*)d_in[5];
  const float* Wp  = (const float*)d_in[6];
  const float* Wf  = (const float*)d_in[7];
  const float* bf  = (const float*)d_in[8];
  const float* ub  = (const float*)d_in[9];
  const float* vb  = (const float*)d_in[10];
  float* out = (float*)d_out;

  static const int attn_smem = SMEM_ATTN_FLOATS * 4;  // ~151 KB
  cudaFuncSetAttribute(attn_fused_kernel,
                       cudaFuncAttributeMaxDynamicSharedMemorySize, attn_smem);

  dim3 gg(8, 32);  // 512/64 n-blocks, 4096/128 m-blocks
  gemm512_kernel<<<gg, 256>>>(q,   Wq, bq,      nullptr, 0);  // qh
  gemm512_kernel<<<gg, 256>>>(k,   Wq, bq,      nullptr, 1);  // kh
  gemm512_kernel<<<gg, 256>>>(v,   Wq, bq,      nullptr, 2);  // vh
  gemm512_kernel<<<gg, 256>>>(pos, Wp, nullptr, nullptr, 3);  // ph

  pscore_kernel<<<dim3(16, 16, 64), 256>>>(vb);

  attn_fused_kernel<<<dim3(32, 64), 256, attn_smem>>>(ub);

  gemm512_kernel<<<gg, 256>>>(nullptr, Wf, bf, out, 4);  // final projection
}

// round 3
// speedup vs baseline: 1.6711x; 1.6711x over previous
#include <cuda_runtime.h>
#include <cstddef>

#define B_ 4
#define T_ 1024
#define D_ 512
#define H_ 16
#define DH_ 32
#define BT_ (B_ * T_)

typedef unsigned long long u64;

// ---- f32x2 packed-math helpers (sm_103a) ----
__device__ __forceinline__ u64 pack2(float x, float y) {
  u64 r; asm("mov.b64 %0, {%1, %2};" : "=l"(r) : "f"(x), "f"(y)); return r;
}
__device__ __forceinline__ void fma2(u64& d, u64 a, u64 b) {
  asm("fma.rn.f32x2 %0, %1, %2, %0;" : "+l"(d) : "l"(a), "l"(b));
}
__device__ __forceinline__ void mul2(u64& d, u64 a) {
  asm("mul.rn.f32x2 %0, %0, %1;" : "+l"(d) : "l"(a));
}
__device__ __forceinline__ float2 unpack2(u64 v) {
  float2 f; asm("mov.b64 {%0, %1}, %2;" : "=f"(f.x), "=f"(f.y) : "l"(v)); return f;
}

// ---- scratch (static device globals; no runtime allocation) ----
__device__ float g_qh[BT_ * D_];
__device__ float g_kh[BT_ * D_];
__device__ float g_vh[BT_ * D_];
__device__ float g_ph[BT_ * D_];
__device__ float g_ctx[BT_ * D_];
__device__ float g_P[(size_t)B_ * H_ * T_ * T_];  // 256 MB, unshifted pos scores

// =====================================================================
// GEMM body: C[128 x 64 tile] = A[M x 512] @ W[512 x 512] (+ bias).
// 256 threads, 8x4 per thread, f32x2 packed FMAs. (Round-2, validated.)
// =====================================================================
__device__ __forceinline__ void gemm_body(
    const float* __restrict__ A, const float* __restrict__ W,
    const float* __restrict__ bias, float* __restrict__ C, int m0, int n0) {
  __shared__ float As[16][132];
  __shared__ float Bs[16][68];

  const int tid = threadIdx.x;
  const int tx = tid & 15, ty = tid >> 4;

  u64 acc[4][4];
#pragma unroll
  for (int i = 0; i < 4; i++)
#pragma unroll
    for (int j = 0; j < 4; j++) acc[i][j] = 0ull;

  for (int k0 = 0; k0 < 512; k0 += 16) {
#pragma unroll
    for (int r = 0; r < 2; r++) {
      int idx = tid + r * 256;
      int m = idx >> 2, kq = (idx & 3) * 4;
      float4 a4 = *reinterpret_cast<const float4*>(&A[(size_t)(m0 + m) * 512 + k0 + kq]);
      As[kq + 0][m] = a4.x; As[kq + 1][m] = a4.y;
      As[kq + 2][m] = a4.z; As[kq + 3][m] = a4.w;
    }
    {
      int kr = tid >> 4, nc = (tid & 15) * 4;
      *reinterpret_cast<float4*>(&Bs[kr][nc]) =
          *reinterpret_cast<const float4*>(&W[(size_t)(k0 + kr) * 512 + n0 + nc]);
    }
    __syncthreads();
#pragma unroll
    for (int kk = 0; kk < 16; kk++) {
      ulonglong2 a01 = *reinterpret_cast<const ulonglong2*>(&As[kk][ty * 8]);
      ulonglong2 a23 = *reinterpret_cast<const ulonglong2*>(&As[kk][ty * 8 + 4]);
      float4 b4 = *reinterpret_cast<const float4*>(&Bs[kk][tx * 4]);
      u64 b0 = pack2(b4.x, b4.x), b1 = pack2(b4.y, b4.y);
      u64 b2 = pack2(b4.z, b4.z), b3 = pack2(b4.w, b4.w);
      fma2(acc[0][0], a01.x, b0); fma2(acc[0][1], a01.x, b1);
      fma2(acc[0][2], a01.x, b2); fma2(acc[0][3], a01.x, b3);
      fma2(acc[1][0], a01.y, b0); fma2(acc[1][1], a01.y, b1);
      fma2(acc[1][2], a01.y, b2); fma2(acc[1][3], a01.y, b3);
      fma2(acc[2][0], a23.x, b0); fma2(acc[2][1], a23.x, b1);
      fma2(acc[2][2], a23.x, b2); fma2(acc[2][3], a23.x, b3);
      fma2(acc[3][0], a23.y, b0); fma2(acc[3][1], a23.y, b1);
      fma2(acc[3][2], a23.y, b2); fma2(acc[3][3], a23.y, b3);
    }
    __syncthreads();
  }

  float4 bb = make_float4(0.f, 0.f, 0.f, 0.f);
  if (bias) bb = *reinterpret_cast<const float4*>(&bias[n0 + tx * 4]);
#pragma unroll
  for (int i = 0; i < 4; i++) {
    float2 p0 = unpack2(acc[i][0]), p1 = unpack2(acc[i][1]);
    float2 p2 = unpack2(acc[i][2]), p3 = unpack2(acc[i][3]);
    float4 r0 = make_float4(p0.x + bb.x, p1.x + bb.y, p2.x + bb.z, p3.x + bb.w);
    float4 r1 = make_float4(p0.y + bb.x, p1.y + bb.y, p2.y + bb.z, p3.y + bb.w);
    const int m = m0 + ty * 8 + 2 * i;
    *reinterpret_cast<float4*>(&C[(size_t)m * 512 + n0 + tx * 4]) = r0;
    *reinterpret_cast<float4*>(&C[(size_t)(m + 1) * 512 + n0 + tx * 4]) = r1;
  }
}

// All 4 projections in ONE launch: blockIdx.z selects {q,k,v,pos}.
__global__ __launch_bounds__(256) void proj_kernel(
    const float* __restrict__ q, const float* __restrict__ k,
    const float* __restrict__ v, const float* __restrict__ pos,
    const float* __restrict__ Wq, const float* __restrict__ bq,
    const float* __restrict__ Wp) {
  const int z = blockIdx.z;
  const float* A = (z == 0) ? q : (z == 1) ? k : (z == 2) ? v : pos;
  float* C = (z == 0) ? g_qh : (z == 1) ? g_kh : (z == 2) ? g_vh : g_ph;
  const float* W = (z < 3) ? Wq : Wp;
  const float* bias = (z < 3) ? bq : nullptr;
  gemm_body(A, W, bias, C, blockIdx.y * 128, blockIdx.x * 64);
}

__global__ __launch_bounds__(256) void final_kernel(
    const float* __restrict__ Wf, const float* __restrict__ bf,
    float* __restrict__ out) {
  gemm_body(g_ctx, Wf, bf, out, blockIdx.y * 128, blockIdx.x * 64);
}

// =====================================================================
// Pos score GEMM: P[bh, t, j] = sum_d (qh[b,t,h,d] + v_bias[h,d]) * ph[b,j,h,d]
// (Round-1/2, validated.)
// =====================================================================
__global__ __launch_bounds__(256) void pscore_kernel(const float* __restrict__ vbias) {
  __shared__ float As[32][68];
  __shared__ float Bs[32][68];
  const int tid = threadIdx.x;
  const int bz = blockIdx.z, b = bz >> 4, h = bz & 15;
  const int t0 = blockIdx.y * 64, j0 = blockIdx.x * 64;

  const int e0 = tid * 2;
#pragma unroll
  for (int e = e0; e < e0 + 2; e++) {
    const int r = e >> 3, seg = (e & 7) * 4;
    float4 a4 = *reinterpret_cast<const float4*>(
        &g_qh[(size_t)(b * T_ + t0 + r) * D_ + h * DH_ + seg]);
    float4 vbv = *reinterpret_cast<const float4*>(&vbias[h * DH_ + seg]);
    float4 b4 = *reinterpret_cast<const float4*>(
        &g_ph[(size_t)(b * T_ + j0 + r) * D_ + h * DH_ + seg]);
    As[seg + 0][r] = a4.x + vbv.x; As[seg + 1][r] = a4.y + vbv.y;
    As[seg + 2][r] = a4.z + vbv.z; As[seg + 3][r] = a4.w + vbv.w;
    Bs[seg + 0][r] = b4.x; Bs[seg + 1][r] = b4.y;
    Bs[seg + 2][r] = b4.z; Bs[seg + 3][r] = b4.w;
  }
  __syncthreads();

  const int tx = tid & 15, ty = tid >> 4;
  u64 acc[4][2];
#pragma unroll
  for (int i = 0; i < 4; i++) { acc[i][0] = 0ull; acc[i][1] = 0ull; }
#pragma unroll
  for (int kk = 0; kk < 32; kk++) {
    float4 a = *reinterpret_cast<const float4*>(&As[kk][ty * 4]);
    ulonglong2 b2 = *reinterpret_cast<const ulonglong2*>(&Bs[kk][tx * 4]);
    u64 a0 = pack2(a.x, a.x), a1 = pack2(a.y, a.y);
    u64 a2 = pack2(a.z, a.z), a3 = pack2(a.w, a.w);
    fma2(acc[0][0], a0, b2.x); fma2(acc[0][1], a0, b2.y);
    fma2(acc[1][0], a1, b2.x); fma2(acc[1][1], a1, b2.y);
    fma2(acc[2][0], a2, b2.x); fma2(acc[2][1], a2, b2.y);
    fma2(acc[3][0], a3, b2.x); fma2(acc[3][1], a3, b2.y);
  }

#pragma unroll
  for (int i = 0; i < 4; i++) {
    const int t = t0 + ty * 4 + i;
    float2 lo = unpack2(acc[i][0]), hi = unpack2(acc[i][1]);
    float4 o = make_float4(lo.x, lo.y, hi.x, hi.y);
    *reinterpret_cast<float4*>(&g_P[((size_t)bz * T_ + t) * T_ + j0 + tx * 4]) = o;
  }
}

// =====================================================================
// Flash-style fused: content score + shift(P) + ONLINE softmax + AV.
// Block = 64 query rows x one (b,h); 16 chunks of 64 keys.
// smem ~44 KB -> >=2 CTAs/SM.
// shift(P)[t,s] = P[t, s-t+1023] (s<=t) ; 0 (s==t+1) ; P[t+1, s-t-2] (s>=t+2)
// =====================================================================
__global__ __launch_bounds__(256) void flash_kernel(const float* __restrict__ ubias) {
  __shared__ float Qs[32 * 68];   // k-major Q+u, resident
  __shared__ float Ks[32 * 68];   // k-major K chunk
  __shared__ float Vs[64 * 36];   // row-major V chunk
  __shared__ float Ps[64 * 68];   // probability tile
  __shared__ float rowX[64];      // per-chunk alpha; finally 1/l

  const int tid = threadIdx.x;
  const int bz = blockIdx.y, b = bz >> 4, h = bz & 15;
  const int t0 = blockIdx.x * 64;

  // load Q (+u_bias) transposed, once
#pragma unroll
  for (int r = 0; r < 2; r++) {
    int idx = tid + r * 256;
    int t = idx >> 3, kq = (idx & 7) * 4;
    float4 q4 = *reinterpret_cast<const float4*>(
        &g_qh[(size_t)(b * T_ + t0 + t) * D_ + h * DH_ + kq]);
    float4 u4 = *reinterpret_cast<const float4*>(&ubias[h * DH_ + kq]);
    Qs[(kq + 0) * 68 + t] = q4.x + u4.x;
    Qs[(kq + 1) * 68 + t] = q4.y + u4.y;
    Qs[(kq + 2) * 68 + t] = q4.z + u4.z;
    Qs[(kq + 3) * 68 + t] = q4.w + u4.w;
  }

  const int tx = tid & 15, ty = tid >> 4;  // score mapping: 4t x 4s
  const int dhg = tid & 7, rg = tid >> 3;  // AV mapping: 2t x 4dh
  const float isd = 0.04419417382415922f;  // 1/sqrt(512)

  float m_st[4], l_st[4];
#pragma unroll
  for (int i = 0; i < 4; i++) { m_st[i] = -3.4e38f; l_st[i] = 0.f; }
  u64 o00 = 0ull, o01 = 0ull, o10 = 0ull, o11 = 0ull;

  for (int c = 0; c < 16; c++) {
    const int s0 = c * 64;
    // ---- load K chunk (transposed) + V chunk ----
#pragma unroll
    for (int r = 0; r < 2; r++) {
      int idx = tid + r * 256;
      int s = idx >> 3, kq = (idx & 7) * 4;
      const size_t gidx = (size_t)(b * T_ + s0 + s) * D_ + h * DH_ + kq;
      float4 k4 = *reinterpret_cast<const float4*>(&g_kh[gidx]);
      Ks[(kq + 0) * 68 + s] = k4.x; Ks[(kq + 1) * 68 + s] = k4.y;
      Ks[(kq + 2) * 68 + s] = k4.z; Ks[(kq + 3) * 68 + s] = k4.w;
      *reinterpret_cast<float4*>(&Vs[s * 36 + kq]) =
          *reinterpret_cast<const float4*>(&g_vh[gidx]);
    }
    __syncthreads();

    // ---- content scores (64x64, K=32) ----
    u64 acc[4][2];
#pragma unroll
    for (int i = 0; i < 4; i++) { acc[i][0] = 0ull; acc[i][1] = 0ull; }
#pragma unroll
    for (int kk = 0; kk < 32; kk++) {
      float4 a4 = *reinterpret_cast<const float4*>(&Qs[kk * 68 + ty * 4]);
      ulonglong2 b2 = *reinterpret_cast<const ulonglong2*>(&Ks[kk * 68 + tx * 4]);
      u64 a0 = pack2(a4.x, a4.x), a1 = pack2(a4.y, a4.y);
      u64 a2 = pack2(a4.z, a4.z), a3 = pack2(a4.w, a4.w);
      fma2(acc[0][0], a0, b2.x); fma2(acc[0][1], a0, b2.y);
      fma2(acc[1][0], a1, b2.x); fma2(acc[1][1], a1, b2.y);
      fma2(acc[2][0], a2, b2.x); fma2(acc[2][1], a2, b2.y);
      fma2(acc[3][0], a3, b2.x); fma2(acc[3][1], a3, b2.y);
    }

    // ---- + shift(P), scale, online softmax update ----
#pragma unroll
    for (int i = 0; i < 4; i++) {
      const int trow = ty * 4 + i;
      const int t = t0 + trow;
      const size_t rowb = ((size_t)bz * T_ + t) * T_;
      float2 lo = unpack2(acc[i][0]), hi = unpack2(acc[i][1]);
      float v[4] = {lo.x, lo.y, hi.x, hi.y};
#pragma unroll
      for (int j = 0; j < 4; j++) {
        const int s = s0 + tx * 4 + j;
        float pv;
        if (s <= t)          pv = g_P[rowb + (s - t + (T_ - 1))];
        else if (s == t + 1) pv = 0.f;
        else                 pv = g_P[rowb + T_ + (s - t - 2)];
        v[j] = (v[j] + pv) * isd;
      }
      float mc = fmaxf(fmaxf(v[0], v[1]), fmaxf(v[2], v[3]));
#pragma unroll
      for (int o = 8; o > 0; o >>= 1) mc = fmaxf(mc, __shfl_xor_sync(0xffffffffu, mc, o));
      const float m_new = fmaxf(m_st[i], mc);
      const float al = __expf(m_st[i] - m_new);
      float p0 = __expf(v[0] - m_new), p1 = __expf(v[1] - m_new);
      float p2 = __expf(v[2] - m_new), p3 = __expf(v[3] - m_new);
      float rs = (p0 + p1) + (p2 + p3);
#pragma unroll
      for (int o = 8; o > 0; o >>= 1) rs += __shfl_xor_sync(0xffffffffu, rs, o);
      l_st[i] = l_st[i] * al + rs;
      m_st[i] = m_new;
      *reinterpret_cast<float4*>(&Ps[trow * 68 + tx * 4]) =
          make_float4(p0, p1, p2, p3);
      if (tx == 0) rowX[trow] = al;
    }
    __syncthreads();

    // ---- AV: rescale accumulators, add P-chunk @ V-chunk ----
    {
      const float a0 = rowX[rg * 2], a1 = rowX[rg * 2 + 1];
      const u64 pa0 = pack2(a0, a0), pa1 = pack2(a1, a1);
      mul2(o00, pa0); mul2(o01, pa0);
      mul2(o10, pa1); mul2(o11, pa1);
      const float* rA = &Ps[(rg * 2) * 68];
      const float* rB = rA + 68;
#pragma unroll 4
      for (int ss = 0; ss < 64; ss += 4) {
        float4 pa = *reinterpret_cast<const float4*>(&rA[ss]);
        float4 pb = *reinterpret_cast<const float4*>(&rB[ss]);
        ulonglong2 v0 = *reinterpret_cast<const ulonglong2*>(&Vs[(ss + 0) * 36 + dhg * 4]);
        ulonglong2 v1 = *reinterpret_cast<const ulonglong2*>(&Vs[(ss + 1) * 36 + dhg * 4]);
        ulonglong2 v2 = *reinterpret_cast<const ulonglong2*>(&Vs[(ss + 2) * 36 + dhg * 4]);
        ulonglong2 v3 = *reinterpret_cast<const ulonglong2*>(&Vs[(ss + 3) * 36 + dhg * 4]);
        fma2(o00, pack2(pa.x, pa.x), v0.x); fma2(o01, pack2(pa.x, pa.x), v0.y);
        fma2(o10, pack2(pb.x, pb.x), v0.x); fma2(o11, pack2(pb.x, pb.x), v0.y);
        fma2(o00, pack2(pa.y, pa.y), v1.x); fma2(o01, pack2(pa.y, pa.y), v1.y);
        fma2(o10, pack2(pb.y, pb.y), v1.x); fma2(o11, pack2(pb.y, pb.y), v1.y);
        fma2(o00, pack2(pa.z, pa.z), v2.x); fma2(o01, pack2(pa.z, pa.z), v2.y);
        fma2(o10, pack2(pb.z, pb.z), v2.x); fma2(o11, pack2(pb.z, pb.z), v2.y);
        fma2(o00, pack2(pa.w, pa.w), v3.x); fma2(o01, pack2(pa.w, pa.w), v3.y);
        fma2(o10, pack2(pb.w, pb.w), v3.x); fma2(o11, pack2(pb.w, pb.w), v3.y);
      }
    }
    __syncthreads();
  }

  // ---- final normalization and store ----
  if (tx == 0) {
#pragma unroll
    for (int i = 0; i < 4; i++) rowX[ty * 4 + i] = 1.0f / l_st[i];
  }
  __syncthreads();
  {
    const float n0 = rowX[rg * 2], n1 = rowX[rg * 2 + 1];
    float2 x0 = unpack2(o00), x1 = unpack2(o01);
    float2 y0 = unpack2(o10), y1 = unpack2(o11);
    float4 r0 = make_float4(x0.x * n0, x0.y * n0, x1.x * n0, x1.y * n0);
    float4 r1 = make_float4(y0.x * n1, y0.y * n1, y1.x * n1, y1.y * n1);
    const size_t base = (size_t)(b * T_ + t0 + rg * 2) * D_ + h * DH_ + dhg * 4;
    *reinterpret_cast<float4*>(&g_ctx[base]) = r0;
    *reinterpret_cast<float4*>(&g_ctx[base + D_]) = r1;
  }
}

// =====================================================================
extern "C" void kernel_launch(void* const* d_in, const int* in_sizes, int n_in,
                              void* d_out, int out_size) {
  const float* q   = (const float*)d_in[0];
  const float* k   = (const float*)d_in[1];
  const float* v   = (const float*)d_in[2];
  const float* pos = (const float*)d_in[3];
  const float* Wq  = (const float*)d_in[4];
  const float* bq  = (const float*)d_in[5];
  const float* Wp  = (const float*)d_in[6];
  const float* Wf  = (const float*)d_in[7];
  const float* bf  = (const float*)d_in[8];
  const float* ub  = (const float*)d_in[9];
  const float* vb  = (const float*)d_in[10];
  float* out = (float*)d_out;

  proj_kernel<<<dim3(8, 32, 4), 256>>>(q, k, v, pos, Wq, bq, Wp);

  pscore_kernel<<<dim3(16, 16, 64), 256>>>(vb);

  flash_kernel<<<dim3(16, 64), 256>>>(ub);

  final_kernel<<<dim3(8, 32), 256>>>(Wf, bf, out);
}

// round 6
// speedup vs baseline: 1.9954x; 1.1941x over previous
#include <cuda_runtime.h>
#include <cuda_bf16.h>
#include <mma.h>
#include <cstddef>
#include <cstdint>

using namespace nvcuda;

#define B_ 4
#define T_ 1024
#define D_ 512
#define H_ 16
#define DH_ 32
#define BT_ (B_ * T_)

typedef unsigned long long u64;

// ---- f32x2 packed-math helpers (sm_103a) ----
__device__ __forceinline__ u64 pack2(float x, float y) {
  u64 r; asm("mov.b64 %0, {%1, %2};" : "=l"(r) : "f"(x), "f"(y)); return r;
}
__device__ __forceinline__ void fma2(u64& d, u64 a, u64 b) {
  asm("fma.rn.f32x2 %0, %1, %2, %0;" : "+l"(d) : "l"(a), "l"(b));
}
__device__ __forceinline__ void mul2(u64& d, u64 a) {
  asm("mul.rn.f32x2 %0, %0, %1;" : "+l"(d) : "l"(a));
}
__device__ __forceinline__ float2 unpack2(u64 v) {
  float2 f; asm("mov.b64 {%0, %1}, %2;" : "=f"(f.x), "=f"(f.y) : "l"(v)); return f;
}

// ---- scratch (static device globals; no runtime allocation) ----
__device__ float g_qh[BT_ * D_];
__device__ float g_kh[BT_ * D_];
__device__ float g_vh[BT_ * D_];
__device__ float g_ph[BT_ * D_];
__device__ float g_ctx[BT_ * D_];
__device__ float g_P[(size_t)B_ * H_ * T_ * T_];  // 256 MB, unshifted pos scores

__device__ __nv_bfloat16 g_inh[4 * BT_ * D_];   // hi(q,k,v,pos)
__device__ __nv_bfloat16 g_inl[4 * BT_ * D_];   // lo
__device__ __nv_bfloat16 g_wth[3 * D_ * D_];    // hi(Wq^T, Wp^T, Wf^T)  [n][k]
__device__ __nv_bfloat16 g_wtl[3 * D_ * D_];
__device__ __nv_bfloat16 g_ctxh[BT_ * D_];
__device__ __nv_bfloat16 g_ctxl[BT_ * D_];
__device__ __nv_bfloat16 g_aqh[BT_ * D_];       // hi(qh + v_bias)
__device__ __nv_bfloat16 g_aql[BT_ * D_];
__device__ __nv_bfloat16 g_phh[BT_ * D_];       // hi(ph)
__device__ __nv_bfloat16 g_phl[BT_ * D_];

// =====================================================================
// fp32 -> bf16 hi/lo split converters
// =====================================================================
__device__ __forceinline__ void split_bf16(float x, __nv_bfloat16& h, __nv_bfloat16& l) {
  h = __float2bfloat16(x);
  l = __float2bfloat16(x - __bfloat162float(h));
}

__global__ __launch_bounds__(256) void convert_inputs_kernel(
    const float* __restrict__ q, const float* __restrict__ k,
    const float* __restrict__ v, const float* __restrict__ pos) {
  const int z = blockIdx.y;
  const float* src = (z == 0) ? q : (z == 1) ? k : (z == 2) ? v : pos;
  __nv_bfloat16* Hh = g_inh + (size_t)z * BT_ * D_;
  __nv_bfloat16* Ll = g_inl + (size_t)z * BT_ * D_;
  const size_t i = ((size_t)blockIdx.x * 256 + threadIdx.x) * 4;
  float4 x = *reinterpret_cast<const float4*>(&src[i]);
  __nv_bfloat162 h0, h1, l0, l1;
  split_bf16(x.x, h0.x, l0.x); split_bf16(x.y, h0.y, l0.y);
  split_bf16(x.z, h1.x, l1.x); split_bf16(x.w, h1.y, l1.y);
  *reinterpret_cast<__nv_bfloat162*>(&Hh[i]) = h0;
  *reinterpret_cast<__nv_bfloat162*>(&Hh[i + 2]) = h1;
  *reinterpret_cast<__nv_bfloat162*>(&Ll[i]) = l0;
  *reinterpret_cast<__nv_bfloat162*>(&Ll[i + 2]) = l1;
}

__global__ __launch_bounds__(256) void convert_ctx_kernel() {
  const size_t i = ((size_t)blockIdx.x * 256 + threadIdx.x) * 4;
  float4 x = *reinterpret_cast<const float4*>(&g_ctx[i]);
  __nv_bfloat162 h0, h1, l0, l1;
  split_bf16(x.x, h0.x, l0.x); split_bf16(x.y, h0.y, l0.y);
  split_bf16(x.z, h1.x, l1.x); split_bf16(x.w, h1.y, l1.y);
  *reinterpret_cast<__nv_bfloat162*>(&g_ctxh[i]) = h0;
  *reinterpret_cast<__nv_bfloat162*>(&g_ctxh[i + 2]) = h1;
  *reinterpret_cast<__nv_bfloat162*>(&g_ctxl[i]) = l0;
  *reinterpret_cast<__nv_bfloat162*>(&g_ctxl[i + 2]) = l1;
}

// split(qh + v_bias_flat) and split(ph)
__global__ __launch_bounds__(256) void convert_attn_kernel(const float* __restrict__ vb) {
  const size_t i = ((size_t)blockIdx.x * 256 + threadIdx.x) * 4;
  const int d = (int)(i & (D_ - 1));
  float4 qv = *reinterpret_cast<const float4*>(&g_qh[i]);
  float4 vbv = *reinterpret_cast<const float4*>(&vb[d]);
  qv.x += vbv.x; qv.y += vbv.y; qv.z += vbv.z; qv.w += vbv.w;
  __nv_bfloat162 h0, h1, l0, l1;
  split_bf16(qv.x, h0.x, l0.x); split_bf16(qv.y, h0.y, l0.y);
  split_bf16(qv.z, h1.x, l1.x); split_bf16(qv.w, h1.y, l1.y);
  *reinterpret_cast<__nv_bfloat162*>(&g_aqh[i]) = h0;
  *reinterpret_cast<__nv_bfloat162*>(&g_aqh[i + 2]) = h1;
  *reinterpret_cast<__nv_bfloat162*>(&g_aql[i]) = l0;
  *reinterpret_cast<__nv_bfloat162*>(&g_aql[i + 2]) = l1;

  float4 pv = *reinterpret_cast<const float4*>(&g_ph[i]);
  split_bf16(pv.x, h0.x, l0.x); split_bf16(pv.y, h0.y, l0.y);
  split_bf16(pv.z, h1.x, l1.x); split_bf16(pv.w, h1.y, l1.y);
  *reinterpret_cast<__nv_bfloat162*>(&g_phh[i]) = h0;
  *reinterpret_cast<__nv_bfloat162*>(&g_phh[i + 2]) = h1;
  *reinterpret_cast<__nv_bfloat162*>(&g_phl[i]) = l0;
  *reinterpret_cast<__nv_bfloat162*>(&g_phl[i + 2]) = l1;
}

// W [k][n] -> Wt [n][k] hi/lo bf16 (32x32 smem tile transpose)
__global__ __launch_bounds__(256) void convert_w_kernel(
    const float* __restrict__ Wq, const float* __restrict__ Wp,
    const float* __restrict__ Wf) {
  const int z = blockIdx.z;
  const float* W = (z == 0) ? Wq : (z == 1) ? Wp : Wf;
  __nv_bfloat16* Hh = g_wth + (size_t)z * D_ * D_;
  __nv_bfloat16* Ll = g_wtl + (size_t)z * D_ * D_;
  __shared__ float tile[32][33];
  const int tx = threadIdx.x & 31, ty = threadIdx.x >> 5;
  const int k0 = blockIdx.y * 32, n0 = blockIdx.x * 32;
#pragma unroll
  for (int r = 0; r < 4; r++)
    tile[ty + 8 * r][tx] = W[(size_t)(k0 + ty + 8 * r) * D_ + n0 + tx];
  __syncthreads();
#pragma unroll
  for (int r = 0; r < 4; r++) {
    const int n = n0 + ty + 8 * r;
    float x = tile[tx][ty + 8 * r];  // = W[k0+tx][n]
    __nv_bfloat16 h, l; split_bf16(x, h, l);
    Hh[(size_t)n * D_ + k0 + tx] = h;
    Ll[(size_t)n * D_ + k0 + tx] = l;
  }
}

// =====================================================================
// wmma split-bf16 GEMM: C[128x64 tile] = A[Mx512] @ Wt^T (+bias)
//   A hi/lo row-major [M][512]; B hi/lo = Wt [n][k] row-major (col_major frag).
//   D = Ah*Bh + Ah*Bl + Al*Bh, fp32 wmma accumulators.
// 256 threads = 8 warps (4m x 2n), warp tile 32x32 (2x2 frags), K chunk 32.
// =====================================================================
#define ALD 40  // smem leading dim (bf16 elems); 40*2=80B rows, 16B aligned

__device__ __forceinline__ void wmma_gemm_body(
    const __nv_bfloat16* __restrict__ Ah, const __nv_bfloat16* __restrict__ Al,
    const __nv_bfloat16* __restrict__ Bh, const __nv_bfloat16* __restrict__ Bl,
    const float* __restrict__ bias, float* __restrict__ C, int m0, int n0) {
  __shared__ __align__(16) char smraw[32768];
  __nv_bfloat16* aH = reinterpret_cast<__nv_bfloat16*>(smraw);
  __nv_bfloat16* aL = aH + 128 * ALD;
  __nv_bfloat16* bH = aL + 128 * ALD;
  __nv_bfloat16* bL = bH + 64 * ALD;

  const int tid = threadIdx.x;
  const int wid = tid >> 5;
  const int wm = wid >> 1, wn = wid & 1;

  wmma::fragment<wmma::accumulator, 16, 16, 16, float> acc[2][2];
#pragma unroll
  for (int i = 0; i < 2; i++)
#pragma unroll
    for (int j = 0; j < 2; j++) wmma::fill_fragment(acc[i][j], 0.f);

  for (int k0 = 0; k0 < 512; k0 += 32) {
#pragma unroll
    for (int r2 = 0; r2 < 2; r2++) {
      const int idx = tid + r2 * 256;
      const int r = idx >> 2, c8 = (idx & 3) * 8;
      const size_t g = (size_t)(m0 + r) * D_ + k0 + c8;
      *reinterpret_cast<uint4*>(&aH[r * ALD + c8]) = *reinterpret_cast<const uint4*>(&Ah[g]);
      *reinterpret_cast<uint4*>(&aL[r * ALD + c8]) = *reinterpret_cast<const uint4*>(&Al[g]);
    }
    {
      const int r = tid >> 2, c8 = (tid & 3) * 8;
      const size_t g = (size_t)(n0 + r) * D_ + k0 + c8;
      *reinterpret_cast<uint4*>(&bH[r * ALD + c8]) = *reinterpret_cast<const uint4*>(&Bh[g]);
      *reinterpret_cast<uint4*>(&bL[r * ALD + c8]) = *reinterpret_cast<const uint4*>(&Bl[g]);
    }
    __syncthreads();
#pragma unroll
    for (int kk = 0; kk < 32; kk += 16) {
      wmma::fragment<wmma::matrix_a, 16, 16, 16, __nv_bfloat16, wmma::row_major> fah[2], fal[2];
      wmma::fragment<wmma::matrix_b, 16, 16, 16, __nv_bfloat16, wmma::col_major> fbh[2], fbl[2];
#pragma unroll
      for (int i = 0; i < 2; i++) {
        wmma::load_matrix_sync(fah[i], &aH[(wm * 32 + i * 16) * ALD + kk], ALD);
        wmma::load_matrix_sync(fal[i], &aL[(wm * 32 + i * 16) * ALD + kk], ALD);
        wmma::load_matrix_sync(fbh[i], &bH[(wn * 32 + i * 16) * ALD + kk], ALD);
        wmma::load_matrix_sync(fbl[i], &bL[(wn * 32 + i * 16) * ALD + kk], ALD);
      }
#pragma unroll
      for (int i = 0; i < 2; i++)
#pragma unroll
        for (int j = 0; j < 2; j++) {
          wmma::mma_sync(acc[i][j], fah[i], fbh[j], acc[i][j]);
          wmma::mma_sync(acc[i][j], fah[i], fbl[j], acc[i][j]);
          wmma::mma_sync(acc[i][j], fal[i], fbh[j], acc[i][j]);
        }
    }
    __syncthreads();
  }

  // epilogue: stage through smem (reuses operand space), add bias, store
  float* Cs = reinterpret_cast<float*>(smraw);  // 128 x 64
#pragma unroll
  for (int i = 0; i < 2; i++)
#pragma unroll
    for (int j = 0; j < 2; j++)
      wmma::store_matrix_sync(&Cs[(wm * 32 + i * 16) * 64 + wn * 32 + j * 16],
                              acc[i][j], 64, wmma::mem_row_major);
  __syncthreads();
#pragma unroll
  for (int r2 = 0; r2 < 8; r2++) {
    const int idx = tid + r2 * 256;
    const int row = idx >> 4, c4 = (idx & 15) * 4;
    float4 o = *reinterpret_cast<const float4*>(&Cs[row * 64 + c4]);
    if (bias) {
      float4 bb = *reinterpret_cast<const float4*>(&bias[n0 + c4]);
      o.x += bb.x; o.y += bb.y; o.z += bb.z; o.w += bb.w;
    }
    *reinterpret_cast<float4*>(&C[(size_t)(m0 + row) * D_ + n0 + c4]) = o;
  }
}

__global__ __launch_bounds__(256) void wmma_proj_kernel(const float* __restrict__ bq) {
  const int z = blockIdx.z;
  const __nv_bfloat16* Ah = g_inh + (size_t)z * BT_ * D_;
  const __nv_bfloat16* Al = g_inl + (size_t)z * BT_ * D_;
  const int ws = (z < 3) ? 0 : 1;
  float* C = (z == 0) ? g_qh : (z == 1) ? g_kh : (z == 2) ? g_vh : g_ph;
  wmma_gemm_body(Ah, Al, g_wth + (size_t)ws * D_ * D_, g_wtl + (size_t)ws * D_ * D_,
                 (z < 3) ? bq : nullptr, C, blockIdx.y * 128, blockIdx.x * 64);
}

__global__ __launch_bounds__(256) void wmma_final_kernel(const float* __restrict__ bf,
                                                         float* __restrict__ out) {
  wmma_gemm_body(g_ctxh, g_ctxl, g_wth + (size_t)2 * D_ * D_, g_wtl + (size_t)2 * D_ * D_,
                 bf, out, blockIdx.y * 128, blockIdx.x * 64);
}

// =====================================================================
// wmma pscore: P[bh, t, j] = sum_d aq[b,t,h,d] * ph[b,j,h,d]   (K = 32)
// Block tile 128t x 128j, 8 warps (4m x 2n), warp tile 32x64 (2x4 frags).
// =====================================================================
__global__ __launch_bounds__(256) void wmma_pscore_kernel() {
  __shared__ __align__(16) __nv_bfloat16 aH[128 * ALD];
  __shared__ __align__(16) __nv_bfloat16 aL[128 * ALD];
  __shared__ __align__(16) __nv_bfloat16 bH[128 * ALD];
  __shared__ __align__(16) __nv_bfloat16 bL[128 * ALD];

  const int tid = threadIdx.x;
  const int wid = tid >> 5;
  const int wm = wid >> 1, wn = wid & 1;
  const int bz = blockIdx.z, b = bz >> 4, h = bz & 15;
  const int t0 = blockIdx.y * 128, j0 = blockIdx.x * 128;

  // A: aq rows t0..t0+127, 32 head dims; B: ph rows j0..j0+127
#pragma unroll
  for (int r2 = 0; r2 < 2; r2++) {
    const int idx = tid + r2 * 256;
    const int r = idx >> 2, c8 = (idx & 3) * 8;
    const size_t ga = (size_t)(b * T_ + t0 + r) * D_ + h * DH_ + c8;
    const size_t gb = (size_t)(b * T_ + j0 + r) * D_ + h * DH_ + c8;
    *reinterpret_cast<uint4*>(&aH[r * ALD + c8]) = *reinterpret_cast<const uint4*>(&g_aqh[ga]);
    *reinterpret_cast<uint4*>(&aL[r * ALD + c8]) = *reinterpret_cast<const uint4*>(&g_aql[ga]);
    *reinterpret_cast<uint4*>(&bH[r * ALD + c8]) = *reinterpret_cast<const uint4*>(&g_phh[gb]);
    *reinterpret_cast<uint4*>(&bL[r * ALD + c8]) = *reinterpret_cast<const uint4*>(&g_phl[gb]);
  }
  __syncthreads();

  wmma::fragment<wmma::accumulator, 16, 16, 16, float> acc[2][4];
#pragma unroll
  for (int i = 0; i < 2; i++)
#pragma unroll
    for (int j = 0; j < 4; j++) wmma::fill_fragment(acc[i][j], 0.f);

#pragma unroll
  for (int kk = 0; kk < 32; kk += 16) {
    wmma::fragment<wmma::matrix_a, 16, 16, 16, __nv_bfloat16, wmma::row_major> fah[2], fal[2];
    wmma::fragment<wmma::matrix_b, 16, 16, 16, __nv_bfloat16, wmma::col_major> fbh[4], fbl[4];
#pragma unroll
    for (int i = 0; i < 2; i++) {
      wmma::load_matrix_sync(fah[i], &aH[(wm * 32 + i * 16) * ALD + kk], ALD);
      wmma::load_matrix_sync(fal[i], &aL[(wm * 32 + i * 16) * ALD + kk], ALD);
    }
#pragma unroll
    for (int j = 0; j < 4; j++) {
      wmma::load_matrix_sync(fbh[j], &bH[(wn * 64 + j * 16) * ALD + kk], ALD);
      wmma::load_matrix_sync(fbl[j], &bL[(wn * 64 + j * 16) * ALD + kk], ALD);
    }
#pragma unroll
    for (int i = 0; i < 2; i++)
#pragma unroll
      for (int j = 0; j < 4; j++) {
        wmma::mma_sync(acc[i][j], fah[i], fbh[j], acc[i][j]);
        wmma::mma_sync(acc[i][j], fah[i], fbl[j], acc[i][j]);
        wmma::mma_sync(acc[i][j], fal[i], fbh[j], acc[i][j]);
      }
  }

  // store directly to g_P (row-major, ldm = 1024)
#pragma unroll
  for (int i = 0; i < 2; i++)
#pragma unroll
    for (int j = 0; j < 4; j++) {
      float* dst = &g_P[((size_t)bz * T_ + t0 + wm * 32 + i * 16) * T_ + j0 + wn * 64 + j * 16];
      wmma::store_matrix_sync(dst, acc[i][j], T_, wmma::mem_row_major);
    }
}

// =====================================================================
// Flash-style fused: content score + shift(P) + online softmax + AV.
// (validated round 3; fp32 f32x2 path)
// =====================================================================
__global__ __launch_bounds__(256) void flash_kernel(const float* __restrict__ ubias) {
  __shared__ float Qs[32 * 68];
  __shared__ float Ks[32 * 68];
  __shared__ float Vs[64 * 36];
  __shared__ float Ps[64 * 68];
  __shared__ float rowX[64];

  const int tid = threadIdx.x;
  const int bz = blockIdx.y, b = bz >> 4, h = bz & 15;
  const int t0 = blockIdx.x * 64;

#pragma unroll
  for (int r = 0; r < 2; r++) {
    int idx = tid + r * 256;
    int t = idx >> 3, kq = (idx & 7) * 4;
    float4 q4 = *reinterpret_cast<const float4*>(
        &g_qh[(size_t)(b * T_ + t0 + t) * D_ + h * DH_ + kq]);
    float4 u4 = *reinterpret_cast<const float4*>(&ubias[h * DH_ + kq]);
    Qs[(kq + 0) * 68 + t] = q4.x + u4.x;
    Qs[(kq + 1) * 68 + t] = q4.y + u4.y;
    Qs[(kq + 2) * 68 + t] = q4.z + u4.z;
    Qs[(kq + 3) * 68 + t] = q4.w + u4.w;
  }

  const int tx = tid & 15, ty = tid >> 4;
  const int dhg = tid & 7, rg = tid >> 3;
  const float isd = 0.04419417382415922f;

  float m_st[4], l_st[4];
#pragma unroll
  for (int i = 0; i < 4; i++) { m_st[i] = -3.4e38f; l_st[i] = 0.f; }
  u64 o00 = 0ull, o01 = 0ull, o10 = 0ull, o11 = 0ull;

  for (int c = 0; c < 16; c++) {
    const int s0 = c * 64;
#pragma unroll
    for (int r = 0; r < 2; r++) {
      int idx = tid + r * 256;
      int s = idx >> 3, kq = (idx & 7) * 4;
      const size_t gidx = (size_t)(b * T_ + s0 + s) * D_ + h * DH_ + kq;
      float4 k4 = *reinterpret_cast<const float4*>(&g_kh[gidx]);
      Ks[(kq + 0) * 68 + s] = k4.x; Ks[(kq + 1) * 68 + s] = k4.y;
      Ks[(kq + 2) * 68 + s] = k4.z; Ks[(kq + 3) * 68 + s] = k4.w;
      *reinterpret_cast<float4*>(&Vs[s * 36 + kq]) =
          *reinterpret_cast<const float4*>(&g_vh[gidx]);
    }
    __syncthreads();

    u64 acc[4][2];
#pragma unroll
    for (int i = 0; i < 4; i++) { acc[i][0] = 0ull; acc[i][1] = 0ull; }
#pragma unroll
    for (int kk = 0; kk < 32; kk++) {
      float4 a4 = *reinterpret_cast<const float4*>(&Qs[kk * 68 + ty * 4]);
      ulonglong2 b2 = *reinterpret_cast<const ulonglong2*>(&Ks[kk * 68 + tx * 4]);
      u64 a0 = pack2(a4.x, a4.x), a1 = pack2(a4.y, a4.y);
      u64 a2 = pack2(a4.z, a4.z), a3 = pack2(a4.w, a4.w);
      fma2(acc[0][0], a0, b2.x); fma2(acc[0][1], a0, b2.y);
      fma2(acc[1][0], a1, b2.x); fma2(acc[1][1], a1, b2.y);
      fma2(acc[2][0], a2, b2.x); fma2(acc[2][1], a2, b2.y);
      fma2(acc[3][0], a3, b2.x); fma2(acc[3][1], a3, b2.y);
    }

#pragma unroll
    for (int i = 0; i < 4; i++) {
      const int trow = ty * 4 + i;
      const int t = t0 + trow;
      const size_t rowb = ((size_t)bz * T_ + t) * T_;
      float2 lo = unpack2(acc[i][0]), hi = unpack2(acc[i][1]);
      float v[4] = {lo.x, lo.y, hi.x, hi.y};
#pragma unroll
      for (int j = 0; j < 4; j++) {
        const int s = s0 + tx * 4 + j;
        float pv;
        if (s <= t)          pv = g_P[rowb + (s - t + (T_ - 1))];
        else if (s == t + 1) pv = 0.f;
        else                 pv = g_P[rowb + T_ + (s - t - 2)];
        v[j] = (v[j] + pv) * isd;
      }
      float mc = fmaxf(fmaxf(v[0], v[1]), fmaxf(v[2], v[3]));
#pragma unroll
      for (int o = 8; o > 0; o >>= 1) mc = fmaxf(mc, __shfl_xor_sync(0xffffffffu, mc, o));
      const float m_new = fmaxf(m_st[i], mc);
      const float al = __expf(m_st[i] - m_new);
      float p0 = __expf(v[0] - m_new), p1 = __expf(v[1] - m_new);
      float p2 = __expf(v[2] - m_new), p3 = __expf(v[3] - m_new);
      float rs = (p0 + p1) + (p2 + p3);
#pragma unroll
      for (int o = 8; o > 0; o >>= 1) rs += __shfl_xor_sync(0xffffffffu, rs, o);
      l_st[i] = l_st[i] * al + rs;
      m_st[i] = m_new;
      *reinterpret_cast<float4*>(&Ps[trow * 68 + tx * 4]) =
          make_float4(p0, p1, p2, p3);
      if (tx == 0) rowX[trow] = al;
    }
    __syncthreads();

    {
      const float a0 = rowX[rg * 2], a1 = rowX[rg * 2 + 1];
      const u64 pa0 = pack2(a0, a0), pa1 = pack2(a1, a1);
      mul2(o00, pa0); mul2(o01, pa0);
      mul2(o10, pa1); mul2(o11, pa1);
      const float* rA = &Ps[(rg * 2) * 68];
      const float* rB = rA + 68;
#pragma unroll 4
      for (int ss = 0; ss < 64; ss += 4) {
        float4 pa = *reinterpret_cast<const float4*>(&rA[ss]);
        float4 pb = *reinterpret_cast<const float4*>(&rB[ss]);
        ulonglong2 v0 = *reinterpret_cast<const ulonglong2*>(&Vs[(ss + 0) * 36 + dhg * 4]);
        ulonglong2 v1 = *reinterpret_cast<const ulonglong2*>(&Vs[(ss + 1) * 36 + dhg * 4]);
        ulonglong2 v2 = *reinterpret_cast<const ulonglong2*>(&Vs[(ss + 2) * 36 + dhg * 4]);
        ulonglong2 v3 = *reinterpret_cast<const ulonglong2*>(&Vs[(ss + 3) * 36 + dhg * 4]);
        fma2(o00, pack2(pa.x, pa.x), v0.x); fma2(o01, pack2(pa.x, pa.x), v0.y);
        fma2(o10, pack2(pb.x, pb.x), v0.x); fma2(o11, pack2(pb.x, pb.x), v0.y);
        fma2(o00, pack2(pa.y, pa.y), v1.x); fma2(o01, pack2(pa.y, pa.y), v1.y);
        fma2(o10, pack2(pb.y, pb.y), v1.x); fma2(o11, pack2(pb.y, pb.y), v1.y);
        fma2(o00, pack2(pa.z, pa.z), v2.x); fma2(o01, pack2(pa.z, pa.z), v2.y);
        fma2(o10, pack2(pb.z, pb.z), v2.x); fma2(o11, pack2(pb.z, pb.z), v2.y);
        fma2(o00, pack2(pa.w, pa.w), v3.x); fma2(o01, pack2(pa.w, pa.w), v3.y);
        fma2(o10, pack2(pb.w, pb.w), v3.x); fma2(o11, pack2(pb.w, pb.w), v3.y);
      }
    }
    __syncthreads();
  }

  if (tx == 0) {
#pragma unroll
    for (int i = 0; i < 4; i++) rowX[ty * 4 + i] = 1.0f / l_st[i];
  }
  __syncthreads();
  {
    const float n0 = rowX[rg * 2], n1 = rowX[rg * 2 + 1];
    float2 x0 = unpack2(o00), x1 = unpack2(o01);
    float2 y0 = unpack2(o10), y1 = unpack2(o11);
    float4 r0 = make_float4(x0.x * n0, x0.y * n0, x1.x * n0, x1.y * n0);
    float4 r1 = make_float4(y0.x * n1, y0.y * n1, y1.x * n1, y1.y * n1);
    const size_t base = (size_t)(b * T_ + t0 + rg * 2) * D_ + h * DH_ + dhg * 4;
    *reinterpret_cast<float4*>(&g_ctx[base]) = r0;
    *reinterpret_cast<float4*>(&g_ctx[base + D_]) = r1;
  }
}

// =====================================================================
extern "C" void kernel_launch(void* const* d_in, const int* in_sizes, int n_in,
                              void* d_out, int out_size) {
  const float* q   = (const float*)d_in[0];
  const float* k   = (const float*)d_in[1];
  const float* v   = (const float*)d_in[2];
  const float* pos = (const float*)d_in[3];
  const float* Wq  = (const float*)d_in[4];
  const float* bq  = (const float*)d_in[5];
  const float* Wp  = (const float*)d_in[6];
  const float* Wf  = (const float*)d_in[7];
  const float* bf  = (const float*)d_in[8];
  const float* ub  = (const float*)d_in[9];
  const float* vb  = (const float*)d_in[10];
  float* out = (float*)d_out;

  convert_inputs_kernel<<<dim3(BT_ * D_ / 1024, 4), 256>>>(q, k, v, pos);
  convert_w_kernel<<<dim3(16, 16, 3), 256>>>(Wq, Wp, Wf);

  wmma_proj_kernel<<<dim3(8, 32, 4), 256>>>(bq);

  convert_attn_kernel<<<BT_ * D_ / 1024, 256>>>(vb);

  wmma_pscore_kernel<<<dim3(8, 8, 64), 256>>>();

  flash_kernel<<<dim3(16, 64), 256>>>(ub);

  convert_ctx_kernel<<<BT_ * D_ / 1024, 256>>>();
  wmma_final_kernel<<<dim3(8, 32), 256>>>(bf, out);
}